// round 3
// baseline (speedup 1.0000x reference)
#include <cuda_runtime.h>
#include <cuda_bf16.h>

#define NN 50000
#define NE 800000
#define DD 64
#define NPAD 50176          // 196 * 256

// Scratch (static device globals)
__device__ float g_neigh[NN * DD];    // holds z = h + segment_sum(h[src])
__device__ float g_z2[NN * DD];
__device__ float g_sum[DD];
__device__ float g_sqs[DD];
__device__ int   g_cnt[NPAD];
__device__ int   g_part[NPAD];
__device__ int   g_btot[196];
__device__ int   g_boff[196];
__device__ int   g_rowstart[NN + 1];
__device__ int   g_cursor[NN];
__device__ int   g_esrc[NE];

// ---------------------------------------------------------------------------
// K0: zero counters + BN stat accumulators
// ---------------------------------------------------------------------------
__global__ void k_zero() {
    int i = blockIdx.x * blockDim.x + threadIdx.x;
    if (i < NPAD) g_cnt[i] = 0;
    if (blockIdx.x == 0 && threadIdx.x < DD) {
        g_sum[threadIdx.x] = 0.f;
        g_sqs[threadIdx.x] = 0.f;
    }
}

// ---------------------------------------------------------------------------
// K1: histogram of dst
// ---------------------------------------------------------------------------
__global__ void k_hist(const int* __restrict__ dst) {
    int e = blockIdx.x * blockDim.x + threadIdx.x;
    if (e < NE) atomicAdd(&g_cnt[dst[e]], 1);
}

// ---------------------------------------------------------------------------
// K2a/K2b/K2c: two-level exclusive scan of g_cnt -> g_rowstart (+cursor copy)
// ---------------------------------------------------------------------------
__device__ __forceinline__ int warp_incl_scan(int v, int lane) {
    #pragma unroll
    for (int o = 1; o < 32; o <<= 1) {
        int t = __shfl_up_sync(0xffffffffu, v, o);
        if (lane >= o) v += t;
    }
    return v;
}

__global__ void k_scan1() {                 // grid 196, block 256
    int i = blockIdx.x * 256 + threadIdx.x;
    int lane = threadIdx.x & 31, w = threadIdx.x >> 5;
    int c = g_cnt[i];
    int v = warp_incl_scan(c, lane);
    __shared__ int ws[8], wso[8];
    if (lane == 31) ws[w] = v;
    __syncthreads();
    if (threadIdx.x == 0) {
        int r = 0;
        #pragma unroll
        for (int k = 0; k < 8; k++) { wso[k] = r; r += ws[k]; }
        g_btot[blockIdx.x] = r;
    }
    __syncthreads();
    g_part[i] = v - c + wso[w];             // block-local exclusive
}

__global__ void k_scan2() {                 // grid 1, block 256
    int b = threadIdx.x;
    int lane = b & 31, w = b >> 5;
    int c = (b < 196) ? g_btot[b] : 0;
    int v = warp_incl_scan(c, lane);
    __shared__ int ws[8], wso[8];
    if (lane == 31) ws[w] = v;
    __syncthreads();
    if (threadIdx.x == 0) {
        int r = 0;
        #pragma unroll
        for (int k = 0; k < 8; k++) { wso[k] = r; r += ws[k]; }
    }
    __syncthreads();
    if (b < 196) g_boff[b] = v - c + wso[w];
}

__global__ void k_scan3() {                 // grid 196, block 256
    int i = blockIdx.x * 256 + threadIdx.x;
    int rs = g_part[i] + g_boff[blockIdx.x];
    if (i < NN) {
        g_rowstart[i] = rs;
        g_cursor[i]   = rs;
    }
    if (i == 0) g_rowstart[NN] = NE;
}

// ---------------------------------------------------------------------------
// K3: fill CSR edge array (src ids grouped by dst)
// ---------------------------------------------------------------------------
__global__ void k_fill(const int* __restrict__ src, const int* __restrict__ dst) {
    int e = blockIdx.x * blockDim.x + threadIdx.x;
    if (e >= NE) return;
    int p = atomicAdd(&g_cursor[dst[e]], 1);
    g_esrc[p] = src[e];
}

// ---------------------------------------------------------------------------
// K4: gather-sum. One warp per node: z[n] = h[n] + sum_{e in-edges} h[src[e]]
//     lanes 0-15 process even edges, 16-31 odd edges; float4 over 64 dims
// ---------------------------------------------------------------------------
__global__ void __launch_bounds__(256) k_gather(const float4* __restrict__ h4) {
    int wid = (blockIdx.x * blockDim.x + threadIdx.x) >> 5;
    if (wid >= NN) return;
    int lane = threadIdx.x & 31;
    int g = lane >> 4, part = lane & 15;
    int start = g_rowstart[wid], end = g_rowstart[wid + 1];
    float4 acc = make_float4(0.f, 0.f, 0.f, 0.f);
    for (int i = start + g; i < end; i += 2) {
        int s = g_esrc[i];
        float4 v = __ldg(&h4[(size_t)s * 16 + part]);
        acc.x += v.x; acc.y += v.y; acc.z += v.z; acc.w += v.w;
    }
    acc.x += __shfl_down_sync(0xffffffffu, acc.x, 16);
    acc.y += __shfl_down_sync(0xffffffffu, acc.y, 16);
    acc.z += __shfl_down_sync(0xffffffffu, acc.z, 16);
    acc.w += __shfl_down_sync(0xffffffffu, acc.w, 16);
    if (g == 0) {
        float4 hv = __ldg(&h4[(size_t)wid * 16 + part]);
        acc.x += hv.x; acc.y += hv.y; acc.z += hv.z; acc.w += hv.w;
        ((float4*)g_neigh)[(size_t)wid * 16 + part] = acc;
    }
}

// ---------------------------------------------------------------------------
// K5: per-node MLP  z2 = relu(z@W1+b1)@W2+b2, fused BN-stat accumulation
// ---------------------------------------------------------------------------
__global__ void __launch_bounds__(256) k_mlp(const float* __restrict__ W1,
                                             const float* __restrict__ b1,
                                             const float* __restrict__ W2,
                                             const float* __restrict__ b2) {
    __shared__ float sZ[128 * DD];
    __shared__ float sW[DD * DD];

    const int tid = threadIdx.x;
    const int node0 = blockIdx.x * 128;
    const int nvalid = min(128, NN - node0);

    for (int i = tid; i < 128 * 16; i += 256) {
        float4 v = (i < nvalid * 16) ? ((const float4*)g_neigh)[node0 * 16 + i]
                                     : make_float4(0.f, 0.f, 0.f, 0.f);
        ((float4*)sZ)[i] = v;
    }
    for (int i = tid; i < DD * DD; i += 256) {
        int k = i >> 6, j = i & 63;
        sW[j * DD + k] = W1[i];
    }
    __syncthreads();

    const int jg = tid & 15;
    const int ng = tid >> 4;
    const int j0 = jg * 4;
    const int n0 = ng * 8;

    float acc[8][4];
    {
        float bb0 = b1[j0], bb1 = b1[j0 + 1], bb2 = b1[j0 + 2], bb3 = b1[j0 + 3];
        #pragma unroll
        for (int n = 0; n < 8; n++) {
            acc[n][0] = bb0; acc[n][1] = bb1; acc[n][2] = bb2; acc[n][3] = bb3;
        }
    }
    #pragma unroll
    for (int k0 = 0; k0 < DD; k0 += 4) {
        float4 w[4];
        #pragma unroll
        for (int c = 0; c < 4; c++)
            w[c] = *(const float4*)&sW[(j0 + c) * DD + k0];
        #pragma unroll
        for (int n = 0; n < 8; n++) {
            float4 a = *(const float4*)&sZ[(n0 + n) * DD + k0];
            #pragma unroll
            for (int c = 0; c < 4; c++) {
                acc[n][c] = fmaf(a.x, w[c].x, acc[n][c]);
                acc[n][c] = fmaf(a.y, w[c].y, acc[n][c]);
                acc[n][c] = fmaf(a.z, w[c].z, acc[n][c]);
                acc[n][c] = fmaf(a.w, w[c].w, acc[n][c]);
            }
        }
    }
    __syncthreads();

    #pragma unroll
    for (int n = 0; n < 8; n++)
        #pragma unroll
        for (int c = 0; c < 4; c++)
            sZ[(n0 + n) * DD + j0 + c] = fmaxf(acc[n][c], 0.f);
    for (int i = tid; i < DD * DD; i += 256) {
        int k = i >> 6, j = i & 63;
        sW[j * DD + k] = W2[i];
    }
    __syncthreads();

    {
        float bb0 = b2[j0], bb1 = b2[j0 + 1], bb2v = b2[j0 + 2], bb3 = b2[j0 + 3];
        #pragma unroll
        for (int n = 0; n < 8; n++) {
            acc[n][0] = bb0; acc[n][1] = bb1; acc[n][2] = bb2v; acc[n][3] = bb3;
        }
    }
    #pragma unroll
    for (int k0 = 0; k0 < DD; k0 += 4) {
        float4 w[4];
        #pragma unroll
        for (int c = 0; c < 4; c++)
            w[c] = *(const float4*)&sW[(j0 + c) * DD + k0];
        #pragma unroll
        for (int n = 0; n < 8; n++) {
            float4 a = *(const float4*)&sZ[(n0 + n) * DD + k0];
            #pragma unroll
            for (int c = 0; c < 4; c++) {
                acc[n][c] = fmaf(a.x, w[c].x, acc[n][c]);
                acc[n][c] = fmaf(a.y, w[c].y, acc[n][c]);
                acc[n][c] = fmaf(a.z, w[c].z, acc[n][c]);
                acc[n][c] = fmaf(a.w, w[c].w, acc[n][c]);
            }
        }
    }

    float s[4] = {0.f, 0.f, 0.f, 0.f};
    float q[4] = {0.f, 0.f, 0.f, 0.f};
    #pragma unroll
    for (int n = 0; n < 8; n++) {
        int node = node0 + n0 + n;
        if (node < NN) {
            ((float4*)g_z2)[node * 16 + jg] =
                make_float4(acc[n][0], acc[n][1], acc[n][2], acc[n][3]);
            #pragma unroll
            for (int c = 0; c < 4; c++) {
                float v = acc[n][c];
                s[c] += v;
                q[c] += v * v;
            }
        }
    }

    __syncthreads();
    float* sRed = sW;
    #pragma unroll
    for (int c = 0; c < 4; c++) {
        sRed[tid * 8 + c] = s[c];
        sRed[tid * 8 + 4 + c] = q[c];
    }
    __syncthreads();
    if (tid < DD) {
        int jg2 = tid >> 2, c2 = tid & 3;
        float a = 0.f, b = 0.f;
        #pragma unroll
        for (int g = 0; g < 16; g++) {
            int t2 = jg2 + g * 16;
            a += sRed[t2 * 8 + c2];
            b += sRed[t2 * 8 + 4 + c2];
        }
        atomicAdd(&g_sum[tid], a);
        atomicAdd(&g_sqs[tid], b);
    }
}

// ---------------------------------------------------------------------------
// K6: out = h + relu( z2 * scale + shift )
// ---------------------------------------------------------------------------
__global__ void k_bn(const float4* __restrict__ h4,
                     const float* __restrict__ gamma,
                     const float* __restrict__ beta,
                     float4* __restrict__ out4) {
    __shared__ float sA[DD], sB[DD];
    if (threadIdx.x < DD) {
        const float invN = 1.0f / (float)NN;
        float m = g_sum[threadIdx.x] * invN;
        float v = g_sqs[threadIdx.x] * invN - m * m;
        float a = gamma[threadIdx.x] * rsqrtf(v + 1e-5f);
        sA[threadIdx.x] = a;
        sB[threadIdx.x] = beta[threadIdx.x] - m * a;
    }
    __syncthreads();
    int i = blockIdx.x * blockDim.x + threadIdx.x;
    if (i < NN * 16) {
        float4 z = ((const float4*)g_z2)[i];
        float4 hv = h4[i];
        int dg = (i & 15) * 4;
        float4 o;
        o.x = hv.x + fmaxf(fmaf(z.x, sA[dg + 0], sB[dg + 0]), 0.f);
        o.y = hv.y + fmaxf(fmaf(z.y, sA[dg + 1], sB[dg + 1]), 0.f);
        o.z = hv.z + fmaxf(fmaf(z.z, sA[dg + 2], sB[dg + 2]), 0.f);
        o.w = hv.w + fmaxf(fmaf(z.w, sA[dg + 3], sB[dg + 3]), 0.f);
        out4[i] = o;
    }
}

// ---------------------------------------------------------------------------
extern "C" void kernel_launch(void* const* d_in, const int* in_sizes, int n_in,
                              void* d_out, int out_size) {
    const float* h     = (const float*)d_in[0];
    const float* W1    = (const float*)d_in[1];
    const float* b1    = (const float*)d_in[2];
    const float* W2    = (const float*)d_in[3];
    const float* b2    = (const float*)d_in[4];
    const float* gamma = (const float*)d_in[5];
    const float* beta  = (const float*)d_in[6];
    const int* src     = (const int*)d_in[7];
    const int* dst     = (const int*)d_in[8];

    (void)in_sizes; (void)n_in; (void)out_size;

    const int eblocks = (NE + 255) / 256;       // 3125

    k_zero<<<NPAD / 256, 256>>>();
    k_hist<<<eblocks, 256>>>(dst);
    k_scan1<<<196, 256>>>();
    k_scan2<<<1, 256>>>();
    k_scan3<<<196, 256>>>();
    k_fill<<<eblocks, 256>>>(src, dst);
    k_gather<<<(NN * 32 + 255) / 256, 256>>>((const float4*)h);
    k_mlp<<<(NN + 127) / 128, 256>>>(W1, b1, W2, b2);
    k_bn<<<(NN * 16 + 255) / 256, 256>>>((const float4*)h, gamma, beta, (float4*)d_out);
}